// round 7
// baseline (speedup 1.0000x reference)
#include <cuda_runtime.h>
#include <cuda_bf16.h>
#include <cstdint>

#define N_NODES 50000
#define F_IN    128
#define F_HID   512
#define MAX_EDGES 1048576
#define NPART ((N_NODES + 255) / 256)   // 196 scan partials

// ---------------------------------------------------------------------------
// Scratch (__device__ globals; allocation-free rule)
// ---------------------------------------------------------------------------
__device__ __align__(16) __nv_bfloat16 g_w1t_hi[F_HID * F_IN];        // W1^T split [512,128]
__device__ __align__(16) __nv_bfloat16 g_w1t_lo[F_HID * F_IN];
__device__ __align__(16) __nv_bfloat16 g_w2t_hi[F_IN * F_HID];        // W2^T split [128,512]
__device__ __align__(16) __nv_bfloat16 g_w2t_lo[F_IN * F_HID];
__device__ int g_deg[N_NODES];          // in-degree histogram
__device__ int g_off[N_NODES + 1];      // exclusive prefix sum
__device__ int g_cur[N_NODES];          // bucket cursors
__device__ int g_part[NPART];           // scan partials
__device__ int g_sorted_src[MAX_EDGES]; // src ids bucketed by dst
__device__ int g_idx_is64;

__device__ __forceinline__ uint32_t smem_to_u32(const void* p) {
    uint32_t a;
    asm("{ .reg .u64 t; cvta.to.shared.u64 t, %1; cvt.u32.u64 %0, t; }"
        : "=r"(a) : "l"(p));
    return a;
}
__device__ __forceinline__ uint32_t pack_bf2(__nv_bfloat16 a, __nv_bfloat16 b) {
    __nv_bfloat162 t(a, b);
    return *reinterpret_cast<uint32_t*>(&t);
}
__device__ __forceinline__ uint32_t sw128(uint32_t byte_off) {
    return byte_off ^ ((byte_off >> 3) & 0x70);
}
// 128x128 bf16 tile stored as two 128x64 column blocks (16KB each, 128B rows, SW128)
__device__ __forceinline__ uint32_t toff128(int r, int k) {
    return (uint32_t)((k >> 6) * 16384) + sw128((uint32_t)(r * 128 + (k & 63) * 2));
}

__device__ __forceinline__ void ldmx4(uint32_t* r, uint32_t addr) {
    asm volatile("ldmatrix.sync.aligned.m8n8.x4.shared.b16 {%0,%1,%2,%3}, [%4];"
                 : "=r"(r[0]), "=r"(r[1]), "=r"(r[2]), "=r"(r[3]) : "r"(addr));
}
__device__ __forceinline__ void ldmx2(uint32_t* r, uint32_t addr) {
    asm volatile("ldmatrix.sync.aligned.m8n8.x2.shared.b16 {%0,%1}, [%2];"
                 : "=r"(r[0]), "=r"(r[1]) : "r"(addr));
}
__device__ __forceinline__ void mma16816(float* c, const uint32_t* a, const uint32_t* b) {
    asm volatile(
        "mma.sync.aligned.m16n8k16.row.col.f32.bf16.bf16.f32 "
        "{%0,%1,%2,%3}, {%4,%5,%6,%7}, {%8,%9}, {%0,%1,%2,%3};"
        : "+f"(c[0]), "+f"(c[1]), "+f"(c[2]), "+f"(c[3])
        : "r"(a[0]), "r"(a[1]), "r"(a[2]), "r"(a[3]), "r"(b[0]), "r"(b[1]));
}

__device__ __forceinline__ int load_idx(const void* ei, int i) {
    return g_idx_is64 ? (int)((const long long*)ei)[i] : ((const int*)ei)[i];
}

// ---------------------------------------------------------------------------
// Kernel A: zero degree histogram + (block 0) edge-index dtype detection
// ---------------------------------------------------------------------------
__global__ void zero_deg_kernel(const int* __restrict__ ei_words)
{
    int i = blockIdx.x * blockDim.x + threadIdx.x;
    if (i < N_NODES) g_deg[i] = 0;
    if (i == 0) {
        int is64 = 1;
        #pragma unroll
        for (int k = 0; k < 64; k++) {
            if (ei_words[2 * k + 1] != 0) { is64 = 0; break; }
        }
        g_idx_is64 = is64;
    }
}

// Kernel B: histogram of dst
__global__ void hist_kernel(const void* __restrict__ ei, int n_edges)
{
    int e = blockIdx.x * blockDim.x + threadIdx.x;
    if (e >= n_edges) return;
    int d = load_idx(ei, n_edges + e);
    if (d >= 0 && d < N_NODES) atomicAdd(&g_deg[d], 1);
}

// ---------------------------------------------------------------------------
// 3-kernel scan: partials -> scan partials -> local scan + offset
// ---------------------------------------------------------------------------
__device__ __forceinline__ int block_excl_scan_256(int v, int tid, int* total_out)
{
    __shared__ int wsum[8];
    const int lane = tid & 31;
    const int wid  = tid >> 5;
    int inc = v;
    #pragma unroll
    for (int d = 1; d < 32; d <<= 1) {
        int t = __shfl_up_sync(0xffffffff, inc, d);
        if (lane >= d) inc += t;
    }
    if (lane == 31) wsum[wid] = inc;
    __syncthreads();
    if (wid == 0 && lane < 8) {
        int ws = wsum[lane];
        #pragma unroll
        for (int d = 1; d < 8; d <<= 1) {
            int t = __shfl_up_sync(0xff, ws, d);
            if (lane >= d) ws += t;
        }
        wsum[lane] = ws;
    }
    __syncthreads();
    int base = (wid > 0) ? wsum[wid - 1] : 0;
    if (total_out) *total_out = wsum[7];
    return base + inc - v;
}

__global__ __launch_bounds__(256)
void scan_part_kernel()
{
    __shared__ int wsum[8];
    int tid = threadIdx.x;
    int i = blockIdx.x * 256 + tid;
    int v = (i < N_NODES) ? g_deg[i] : 0;
    int lane = tid & 31, wid = tid >> 5;
    #pragma unroll
    for (int d = 16; d > 0; d >>= 1)
        v += __shfl_down_sync(0xffffffff, v, d);
    if (lane == 0) wsum[wid] = v;
    __syncthreads();
    if (tid == 0) {
        int t = 0;
        #pragma unroll
        for (int w = 0; w < 8; w++) t += wsum[w];
        g_part[blockIdx.x] = t;
    }
}

__global__ __launch_bounds__(256)
void scan_mid_kernel()
{
    int tid = threadIdx.x;
    int v = (tid < NPART) ? g_part[tid] : 0;
    int total;
    int excl = block_excl_scan_256(v, tid, &total);
    if (tid < NPART) g_part[tid] = excl;
    if (tid == 0) g_off[N_NODES] = total;
}

__global__ __launch_bounds__(256)
void scan_final_kernel()
{
    int tid = threadIdx.x;
    int i = blockIdx.x * 256 + tid;
    int v = (i < N_NODES) ? g_deg[i] : 0;
    int excl = block_excl_scan_256(v, tid, nullptr);
    if (i < N_NODES) {
        int o = g_part[blockIdx.x] + excl;
        g_off[i] = o;
        g_cur[i] = o;
    }
}

// Kernel D: bucket src by dst
__global__ void bucket_kernel(const void* __restrict__ ei, int n_edges)
{
    int e = blockIdx.x * blockDim.x + threadIdx.x;
    if (e >= n_edges) return;
    int s = load_idx(ei, e);
    int d = load_idx(ei, n_edges + e);
    if (s < 0 || s >= N_NODES || d < 0 || d >= N_NODES) return;
    int pos = atomicAdd(&g_cur[d], 1);
    if (pos < MAX_EDGES) g_sorted_src[pos] = s;
}

// ---------------------------------------------------------------------------
// Kernel: weight transpose + hi/lo bf16 split. out[n*K+k] = split(W[k*N+n]).
// ---------------------------------------------------------------------------
__global__ void transpose_split_kernel(const float* __restrict__ W, int K, int N,
                                       __nv_bfloat16* __restrict__ out_hi,
                                       __nv_bfloat16* __restrict__ out_lo)
{
    int idx = blockIdx.x * blockDim.x + threadIdx.x;
    if (idx >= K * N) return;
    int n = idx / K, k = idx % K;
    float v = W[(size_t)k * N + n];
    __nv_bfloat16 h = __float2bfloat16(v);
    out_hi[idx] = h;
    out_lo[idx] = __float2bfloat16(v - __bfloat162float(h));
}

// ---------------------------------------------------------------------------
// Fused GIN kernel: gather + MLP, one CTA per 128-row node block.
//   A-tile = (1+eps)*x[node] + sum_{src in bucket} x[src]  (gathered in-kernel,
//   split to bf16 hi/lo SMEM). Then: out = relu(A@W1+b1)@W2 + b2.
// h0 and h1 never touch global memory.
// ---------------------------------------------------------------------------
__global__ __launch_bounds__(256, 1)
void fused_gin_kernel(const float* __restrict__ x,
                      const float* __restrict__ eps,
                      const __nv_bfloat16* __restrict__ W1t_hi,
                      const __nv_bfloat16* __restrict__ W1t_lo,
                      const float* __restrict__ b1,
                      const __nv_bfloat16* __restrict__ W2t_hi,
                      const __nv_bfloat16* __restrict__ W2t_lo,
                      const float* __restrict__ b2,
                      float* __restrict__ out,
                      int M)
{
    constexpr int SM_A_HI = 0;
    constexpr int SM_A_LO = 32768;
    constexpr int SM_W_HI = 65536;
    constexpr int SM_W_LO = 65536 + 32768;
    constexpr int SM_H_HI = 131072;
    constexpr int SM_H_LO = 131072 + 32768;

    extern __shared__ __align__(1024) char smem[];
    const uint32_t sbase = smem_to_u32(smem);

    const int tid  = threadIdx.x;
    const int wid  = tid >> 5;
    const int lane = tid & 31;
    const int wm   = wid >> 2;
    const int wn   = wid & 3;
    const int bm   = blockIdx.x * 128;

    const int a_row = lane & 15;
    const int a_kh  = (lane >> 4) & 1;
    const int b_row = lane & 7;
    const int b_kh  = (lane >> 3) & 1;
    const int er    = lane >> 2;
    const int ec    = (lane & 3) * 2;

    // ---- gather phase: warp w builds rows [w*16, w*16+16) of the A tile ----
    {
        const float s = 1.0f + *eps;
        for (int rr = 0; rr < 16; rr++) {
            const int r  = wid * 16 + rr;
            const int gr = bm + r;
            float4 a0 = make_float4(0.f, 0.f, 0.f, 0.f);
            if (gr < M) {
                const float4 xv = *reinterpret_cast<const float4*>(
                    x + (size_t)gr * F_IN + lane * 4);
                a0.x = xv.x * s; a0.y = xv.y * s; a0.z = xv.z * s; a0.w = xv.w * s;
                const int beg = g_off[gr];
                const int end = g_off[gr + 1];
                float4 a1 = make_float4(0.f, 0.f, 0.f, 0.f);
                float4 a2 = make_float4(0.f, 0.f, 0.f, 0.f);
                float4 a3 = make_float4(0.f, 0.f, 0.f, 0.f);
                int e = beg;
                for (; e + 3 < end; e += 4) {
                    int s0 = g_sorted_src[e];
                    int s1 = g_sorted_src[e + 1];
                    int s2 = g_sorted_src[e + 2];
                    int s3 = g_sorted_src[e + 3];
                    float4 v0 = *reinterpret_cast<const float4*>(x + (size_t)s0 * F_IN + lane * 4);
                    float4 v1 = *reinterpret_cast<const float4*>(x + (size_t)s1 * F_IN + lane * 4);
                    float4 v2 = *reinterpret_cast<const float4*>(x + (size_t)s2 * F_IN + lane * 4);
                    float4 v3 = *reinterpret_cast<const float4*>(x + (size_t)s3 * F_IN + lane * 4);
                    a0.x += v0.x; a0.y += v0.y; a0.z += v0.z; a0.w += v0.w;
                    a1.x += v1.x; a1.y += v1.y; a1.z += v1.z; a1.w += v1.w;
                    a2.x += v2.x; a2.y += v2.y; a2.z += v2.z; a2.w += v2.w;
                    a3.x += v3.x; a3.y += v3.y; a3.z += v3.z; a3.w += v3.w;
                }
                for (; e < end; e++) {
                    int s0 = g_sorted_src[e];
                    float4 v0 = *reinterpret_cast<const float4*>(x + (size_t)s0 * F_IN + lane * 4);
                    a0.x += v0.x; a0.y += v0.y; a0.z += v0.z; a0.w += v0.w;
                }
                a0.x += a1.x + a2.x + a3.x;
                a0.y += a1.y + a2.y + a3.y;
                a0.z += a1.z + a2.z + a3.z;
                a0.w += a1.w + a2.w + a3.w;
            }
            __nv_bfloat16 h0b = __float2bfloat16(a0.x);
            __nv_bfloat16 h1b = __float2bfloat16(a0.y);
            __nv_bfloat16 h2b = __float2bfloat16(a0.z);
            __nv_bfloat16 h3b = __float2bfloat16(a0.w);
            uint2 hv, lv;
            hv.x = pack_bf2(h0b, h1b);
            hv.y = pack_bf2(h2b, h3b);
            lv.x = pack_bf2(__float2bfloat16(a0.x - __bfloat162float(h0b)),
                            __float2bfloat16(a0.y - __bfloat162float(h1b)));
            lv.y = pack_bf2(__float2bfloat16(a0.z - __bfloat162float(h2b)),
                            __float2bfloat16(a0.w - __bfloat162float(h3b)));
            uint32_t off = toff128(r, lane * 4);
            *reinterpret_cast<uint2*>(smem + SM_A_HI + off) = hv;
            *reinterpret_cast<uint2*>(smem + SM_A_LO + off) = lv;
        }
    }

    float acc_out[4][4][4];
    #pragma unroll
    for (int i = 0; i < 4; i++)
        #pragma unroll
        for (int j = 0; j < 4; j++)
            #pragma unroll
            for (int q = 0; q < 4; q++)
                acc_out[i][j][q] = 0.f;

    for (int c = 0; c < 4; c++) {
        __syncthreads();
        #pragma unroll
        for (int it = 0; it < 8; it++) {
            int slot = tid + it * 256;
            int r  = slot >> 4;
            int c8 = slot & 15;
            size_t g = (size_t)(c * 128 + r) * F_IN + c8 * 8;
            uint32_t off = toff128(r, c8 * 8);
            *reinterpret_cast<uint4*>(smem + SM_W_HI + off) =
                *reinterpret_cast<const uint4*>(W1t_hi + g);
            *reinterpret_cast<uint4*>(smem + SM_W_LO + off) =
                *reinterpret_cast<const uint4*>(W1t_lo + g);
        }
        __syncthreads();

        float acc_h[4][4][4];
        #pragma unroll
        for (int i = 0; i < 4; i++)
            #pragma unroll
            for (int j = 0; j < 4; j++)
                #pragma unroll
                for (int q = 0; q < 4; q++)
                    acc_h[i][j][q] = 0.f;

        #pragma unroll
        for (int ks = 0; ks < 8; ks++) {
            uint32_t bh[4][2], bl[4][2];
            #pragma unroll
            for (int nt = 0; nt < 4; nt++) {
                int n = wn * 32 + nt * 8 + b_row;
                uint32_t off = toff128(n, ks * 16 + b_kh * 8);
                ldmx2(bh[nt], sbase + SM_W_HI + off);
                ldmx2(bl[nt], sbase + SM_W_LO + off);
            }
            #pragma unroll
            for (int mt = 0; mt < 4; mt++) {
                int m = wm * 64 + mt * 16 + a_row;
                uint32_t off = toff128(m, ks * 16 + a_kh * 8);
                uint32_t ah[4], al[4];
                ldmx4(ah, sbase + SM_A_HI + off);
                ldmx4(al, sbase + SM_A_LO + off);
                #pragma unroll
                for (int nt = 0; nt < 4; nt++) {
                    mma16816(acc_h[mt][nt], ah, bh[nt]);
                    mma16816(acc_h[mt][nt], ah, bl[nt]);
                    mma16816(acc_h[mt][nt], al, bh[nt]);
                }
            }
        }
        __syncthreads();

        #pragma unroll
        for (int mt = 0; mt < 4; mt++) {
            int lr0 = wm * 64 + mt * 16 + er;
            #pragma unroll
            for (int nt = 0; nt < 4; nt++) {
                int lc = wn * 32 + nt * 8 + ec;
                float bia0 = b1[c * 128 + lc];
                float bia1 = b1[c * 128 + lc + 1];
                #pragma unroll
                for (int h = 0; h < 2; h++) {
                    float v0 = fmaxf(acc_h[mt][nt][2 * h + 0] + bia0, 0.f);
                    float v1 = fmaxf(acc_h[mt][nt][2 * h + 1] + bia1, 0.f);
                    __nv_bfloat16 hh0 = __float2bfloat16(v0);
                    __nv_bfloat16 hh1 = __float2bfloat16(v1);
                    uint32_t off = toff128(lr0 + h * 8, lc);
                    *reinterpret_cast<uint32_t*>(smem + SM_H_HI + off) = pack_bf2(hh0, hh1);
                    *reinterpret_cast<uint32_t*>(smem + SM_H_LO + off) =
                        pack_bf2(__float2bfloat16(v0 - __bfloat162float(hh0)),
                                 __float2bfloat16(v1 - __bfloat162float(hh1)));
                }
            }
        }
        #pragma unroll
        for (int it = 0; it < 8; it++) {
            int slot = tid + it * 256;
            int r  = slot >> 4;
            int c8 = slot & 15;
            size_t g = (size_t)r * F_HID + c * 128 + c8 * 8;
            uint32_t off = toff128(r, c8 * 8);
            *reinterpret_cast<uint4*>(smem + SM_W_HI + off) =
                *reinterpret_cast<const uint4*>(W2t_hi + g);
            *reinterpret_cast<uint4*>(smem + SM_W_LO + off) =
                *reinterpret_cast<const uint4*>(W2t_lo + g);
        }
        __syncthreads();

        #pragma unroll
        for (int ks = 0; ks < 8; ks++) {
            uint32_t bh[4][2], bl[4][2];
            #pragma unroll
            for (int nt = 0; nt < 4; nt++) {
                int n = wn * 32 + nt * 8 + b_row;
                uint32_t off = toff128(n, ks * 16 + b_kh * 8);
                ldmx2(bh[nt], sbase + SM_W_HI + off);
                ldmx2(bl[nt], sbase + SM_W_LO + off);
            }
            #pragma unroll
            for (int mt = 0; mt < 4; mt++) {
                int m = wm * 64 + mt * 16 + a_row;
                uint32_t off = toff128(m, ks * 16 + a_kh * 8);
                uint32_t ah[4], al[4];
                ldmx4(ah, sbase + SM_H_HI + off);
                ldmx4(al, sbase + SM_H_LO + off);
                #pragma unroll
                for (int nt = 0; nt < 4; nt++) {
                    mma16816(acc_out[mt][nt], ah, bh[nt]);
                    mma16816(acc_out[mt][nt], ah, bl[nt]);
                    mma16816(acc_out[mt][nt], al, bh[nt]);
                }
            }
        }
    }

    #pragma unroll
    for (int mt = 0; mt < 4; mt++) {
        const int row0 = bm + wm * 64 + mt * 16 + er;
        #pragma unroll
        for (int nt = 0; nt < 4; nt++) {
            const int col = wn * 32 + nt * 8 + ec;
            const float bia0 = b2[col], bia1 = b2[col + 1];
            #pragma unroll
            for (int h = 0; h < 2; h++) {
                const int row = row0 + h * 8;
                if (row >= M) continue;
                float2 v;
                v.x = acc_out[mt][nt][2 * h + 0] + bia0;
                v.y = acc_out[mt][nt][2 * h + 1] + bia1;
                *reinterpret_cast<float2*>(out + (size_t)row * F_IN + col) = v;
            }
        }
    }
}

// ---------------------------------------------------------------------------
// Launch
// ---------------------------------------------------------------------------
extern "C" void kernel_launch(void* const* d_in, const int* in_sizes, int n_in,
                              void* d_out, int out_size)
{
    const float* x   = (const float*)d_in[0];
    const void*  ei  = d_in[1];
    const float* W1  = (const float*)d_in[2];
    const float* b1  = (const float*)d_in[3];
    const float* W2  = (const float*)d_in[4];
    const float* b2  = (const float*)d_in[5];
    const float* eps = (const float*)d_in[6];
    float* out = (float*)d_out;

    const int n_edges = in_sizes[1] / 2;

    __nv_bfloat16 *w1th, *w1tl, *w2th, *w2tl;
    cudaGetSymbolAddress((void**)&w1th, g_w1t_hi);
    cudaGetSymbolAddress((void**)&w1tl, g_w1t_lo);
    cudaGetSymbolAddress((void**)&w2th, g_w2t_hi);
    cudaGetSymbolAddress((void**)&w2tl, g_w2t_lo);

    // 0) zero histogram + dtype detect; weight prep
    zero_deg_kernel<<<(N_NODES + 255) / 256, 256>>>((const int*)ei);
    transpose_split_kernel<<<(F_IN * F_HID + 255) / 256, 256>>>(W1, F_IN, F_HID, w1th, w1tl);
    transpose_split_kernel<<<(F_HID * F_IN + 255) / 256, 256>>>(W2, F_HID, F_IN, w2th, w2tl);

    // 1) counting sort of edges by dst
    hist_kernel<<<(n_edges + 255) / 256, 256>>>(ei, n_edges);
    scan_part_kernel<<<NPART, 256>>>();
    scan_mid_kernel<<<1, 256>>>();
    scan_final_kernel<<<NPART, 256>>>();
    bucket_kernel<<<(n_edges + 255) / 256, 256>>>(ei, n_edges);

    // 2) fused gather + MLP
    {
        constexpr int SMEM = 196608;   // 192 KB
        cudaFuncSetAttribute(fused_gin_kernel,
                             cudaFuncAttributeMaxDynamicSharedMemorySize, SMEM);
        const int mtiles = (N_NODES + 127) / 128;   // 391
        fused_gin_kernel<<<mtiles, 256, SMEM>>>(
            x, eps, w1th, w1tl, b1, w2th, w2tl, b2, out, N_NODES);
    }
}

// round 9
// speedup vs baseline: 1.2307x; 1.2307x over previous
#include <cuda_runtime.h>
#include <cuda_bf16.h>
#include <cstdint>

#define N_NODES 50000
#define F_IN    128
#define F_HID   512
#define MAX_EDGES 1048576
#define NPART ((N_NODES + 255) / 256)   // 196 scan partials

// ---------------------------------------------------------------------------
// Scratch (__device__ globals; allocation-free rule)
// ---------------------------------------------------------------------------
__device__ __align__(16) __nv_bfloat16 g_h0_hi[N_NODES * F_IN];       // split h0
__device__ __align__(16) __nv_bfloat16 g_h0_lo[N_NODES * F_IN];
__device__ __align__(16) __nv_bfloat16 g_w1t_hi[F_HID * F_IN];        // W1^T split [512,128]
__device__ __align__(16) __nv_bfloat16 g_w1t_lo[F_HID * F_IN];
__device__ __align__(16) __nv_bfloat16 g_w2t_hi[F_IN * F_HID];        // W2^T split [128,512]
__device__ __align__(16) __nv_bfloat16 g_w2t_lo[F_IN * F_HID];
__device__ int g_deg[N_NODES];          // in-degree histogram
__device__ int g_off[N_NODES + 1];      // exclusive prefix sum
__device__ int g_cur[N_NODES];          // bucket cursors
__device__ int g_part[NPART];           // scan partials
__device__ int g_sorted_src[MAX_EDGES]; // src ids bucketed by dst
__device__ int g_idx_is64;

__device__ __forceinline__ uint32_t smem_to_u32(const void* p) {
    uint32_t a;
    asm("{ .reg .u64 t; cvta.to.shared.u64 t, %1; cvt.u32.u64 %0, t; }"
        : "=r"(a) : "l"(p));
    return a;
}
__device__ __forceinline__ uint32_t pack_bf2(__nv_bfloat16 a, __nv_bfloat16 b) {
    __nv_bfloat162 t(a, b);
    return *reinterpret_cast<uint32_t*>(&t);
}
__device__ __forceinline__ uint32_t sw128(uint32_t byte_off) {
    return byte_off ^ ((byte_off >> 3) & 0x70);
}
// 128x128 bf16 tile stored as two 128x64 column blocks (16KB each, 128B rows, SW128)
__device__ __forceinline__ uint32_t toff128(int r, int k) {
    return (uint32_t)((k >> 6) * 16384) + sw128((uint32_t)(r * 128 + (k & 63) * 2));
}

__device__ __forceinline__ void ldmx4(uint32_t* r, uint32_t addr) {
    asm volatile("ldmatrix.sync.aligned.m8n8.x4.shared.b16 {%0,%1,%2,%3}, [%4];"
                 : "=r"(r[0]), "=r"(r[1]), "=r"(r[2]), "=r"(r[3]) : "r"(addr));
}
__device__ __forceinline__ void ldmx2(uint32_t* r, uint32_t addr) {
    asm volatile("ldmatrix.sync.aligned.m8n8.x2.shared.b16 {%0,%1}, [%2];"
                 : "=r"(r[0]), "=r"(r[1]) : "r"(addr));
}
__device__ __forceinline__ void mma16816(float* c, const uint32_t* a, const uint32_t* b) {
    asm volatile(
        "mma.sync.aligned.m16n8k16.row.col.f32.bf16.bf16.f32 "
        "{%0,%1,%2,%3}, {%4,%5,%6,%7}, {%8,%9}, {%0,%1,%2,%3};"
        : "+f"(c[0]), "+f"(c[1]), "+f"(c[2]), "+f"(c[3])
        : "r"(a[0]), "r"(a[1]), "r"(a[2]), "r"(a[3]), "r"(b[0]), "r"(b[1]));
}

__device__ __forceinline__ int load_idx(const void* ei, int i) {
    return g_idx_is64 ? (int)((const long long*)ei)[i] : ((const int*)ei)[i];
}

// ---------------------------------------------------------------------------
// Kernel A: zero degree histogram + (thread 0) edge-index dtype detection
// ---------------------------------------------------------------------------
__global__ void zero_deg_kernel(const int* __restrict__ ei_words)
{
    int i = blockIdx.x * blockDim.x + threadIdx.x;
    if (i < N_NODES) g_deg[i] = 0;
    if (i == 0) {
        int is64 = 1;
        #pragma unroll
        for (int k = 0; k < 64; k++) {
            if (ei_words[2 * k + 1] != 0) { is64 = 0; break; }
        }
        g_idx_is64 = is64;
    }
}

// Kernel B: histogram of dst (4 edges per thread)
__global__ void hist_kernel(const void* __restrict__ ei, int n_edges)
{
    int base = blockIdx.x * 1024;
    #pragma unroll
    for (int k = 0; k < 4; k++) {
        int e = base + k * 256 + threadIdx.x;
        if (e < n_edges) {
            int d = load_idx(ei, n_edges + e);
            if (d >= 0 && d < N_NODES) atomicAdd(&g_deg[d], 1);
        }
    }
}

// ---------------------------------------------------------------------------
// 3-kernel scan: partials -> scan partials -> local scan + offset
// ---------------------------------------------------------------------------
__device__ __forceinline__ int block_excl_scan_256(int v, int tid, int* total_out)
{
    __shared__ int wsum[8];
    const int lane = tid & 31;
    const int wid  = tid >> 5;
    int inc = v;
    #pragma unroll
    for (int d = 1; d < 32; d <<= 1) {
        int t = __shfl_up_sync(0xffffffff, inc, d);
        if (lane >= d) inc += t;
    }
    if (lane == 31) wsum[wid] = inc;
    __syncthreads();
    if (wid == 0 && lane < 8) {
        int ws = wsum[lane];
        #pragma unroll
        for (int d = 1; d < 8; d <<= 1) {
            int t = __shfl_up_sync(0xff, ws, d);
            if (lane >= d) ws += t;
        }
        wsum[lane] = ws;
    }
    __syncthreads();
    int base = (wid > 0) ? wsum[wid - 1] : 0;
    if (total_out) *total_out = wsum[7];
    return base + inc - v;
}

__global__ __launch_bounds__(256)
void scan_part_kernel()
{
    __shared__ int wsum[8];
    int tid = threadIdx.x;
    int i = blockIdx.x * 256 + tid;
    int v = (i < N_NODES) ? g_deg[i] : 0;
    int lane = tid & 31, wid = tid >> 5;
    #pragma unroll
    for (int d = 16; d > 0; d >>= 1)
        v += __shfl_down_sync(0xffffffff, v, d);
    if (lane == 0) wsum[wid] = v;
    __syncthreads();
    if (tid == 0) {
        int t = 0;
        #pragma unroll
        for (int w = 0; w < 8; w++) t += wsum[w];
        g_part[blockIdx.x] = t;
    }
}

__global__ __launch_bounds__(256)
void scan_mid_kernel()
{
    int tid = threadIdx.x;
    int v = (tid < NPART) ? g_part[tid] : 0;
    int total;
    int excl = block_excl_scan_256(v, tid, &total);
    if (tid < NPART) g_part[tid] = excl;
    if (tid == 0) g_off[N_NODES] = total;
}

__global__ __launch_bounds__(256)
void scan_final_kernel()
{
    int tid = threadIdx.x;
    int i = blockIdx.x * 256 + tid;
    int v = (i < N_NODES) ? g_deg[i] : 0;
    int excl = block_excl_scan_256(v, tid, nullptr);
    if (i < N_NODES) {
        int o = g_part[blockIdx.x] + excl;
        g_off[i] = o;
        g_cur[i] = o;
    }
}

// Kernel D: bucket src by dst (4 edges per thread)
__global__ void bucket_kernel(const void* __restrict__ ei, int n_edges)
{
    int base = blockIdx.x * 1024;
    #pragma unroll
    for (int k = 0; k < 4; k++) {
        int e = base + k * 256 + threadIdx.x;
        if (e < n_edges) {
            int s = load_idx(ei, e);
            int d = load_idx(ei, n_edges + e);
            if (s >= 0 && s < N_NODES && d >= 0 && d < N_NODES) {
                int pos = atomicAdd(&g_cur[d], 1);
                if (pos < MAX_EDGES) g_sorted_src[pos] = s;
            }
        }
    }
}

// ---------------------------------------------------------------------------
// Kernel: weight transpose + hi/lo bf16 split. out[n*K+k] = split(W[k*N+n]).
// ---------------------------------------------------------------------------
__global__ void transpose_split_kernel(const float* __restrict__ W, int K, int N,
                                       __nv_bfloat16* __restrict__ out_hi,
                                       __nv_bfloat16* __restrict__ out_lo)
{
    int idx = blockIdx.x * blockDim.x + threadIdx.x;
    if (idx >= K * N) return;
    int n = idx / K, k = idx % K;
    float v = W[(size_t)k * N + n];
    __nv_bfloat16 h = __float2bfloat16(v);
    out_hi[idx] = h;
    out_lo[idx] = __float2bfloat16(v - __bfloat162float(h));
}

// ---------------------------------------------------------------------------
// Kernel E: gather-accumulate, warp per node, lane-parallel index loads.
//   h0[n] = (1+eps)*x[n] + sum_{e in bucket(n)} x[src[e]]  -> split bf16 hi/lo
// ---------------------------------------------------------------------------
__global__ __launch_bounds__(256)
void gather_kernel(const float* __restrict__ x,
                   const float* __restrict__ eps,
                   __nv_bfloat16* __restrict__ h_hi,
                   __nv_bfloat16* __restrict__ h_lo)
{
    const int warp = (blockIdx.x * blockDim.x + threadIdx.x) >> 5;
    if (warp >= N_NODES) return;
    const int lane = threadIdx.x & 31;

    const int beg = g_off[warp];
    const int end = g_off[warp + 1];
    const float s = 1.0f + *eps;

    float4 xv = *reinterpret_cast<const float4*>(x + (size_t)warp * F_IN + lane * 4);
    float4 a0, a1, a2, a3;
    a0.x = xv.x * s; a0.y = xv.y * s; a0.z = xv.z * s; a0.w = xv.w * s;
    a1 = make_float4(0.f, 0.f, 0.f, 0.f);
    a2 = make_float4(0.f, 0.f, 0.f, 0.f);
    a3 = make_float4(0.f, 0.f, 0.f, 0.f);

    for (int b = beg; b < end; b += 32) {
        const int n = min(32, end - b);
        // lane-parallel, coalesced index load; broadcast via shfl
        int idx = (b + lane < end) ? g_sorted_src[b + lane] : 0;
        int j = 0;
        for (; j + 3 < n; j += 4) {
            int s0 = __shfl_sync(0xffffffff, idx, j);
            int s1 = __shfl_sync(0xffffffff, idx, j + 1);
            int s2 = __shfl_sync(0xffffffff, idx, j + 2);
            int s3 = __shfl_sync(0xffffffff, idx, j + 3);
            float4 v0 = *reinterpret_cast<const float4*>(x + (size_t)s0 * F_IN + lane * 4);
            float4 v1 = *reinterpret_cast<const float4*>(x + (size_t)s1 * F_IN + lane * 4);
            float4 v2 = *reinterpret_cast<const float4*>(x + (size_t)s2 * F_IN + lane * 4);
            float4 v3 = *reinterpret_cast<const float4*>(x + (size_t)s3 * F_IN + lane * 4);
            a0.x += v0.x; a0.y += v0.y; a0.z += v0.z; a0.w += v0.w;
            a1.x += v1.x; a1.y += v1.y; a1.z += v1.z; a1.w += v1.w;
            a2.x += v2.x; a2.y += v2.y; a2.z += v2.z; a2.w += v2.w;
            a3.x += v3.x; a3.y += v3.y; a3.z += v3.z; a3.w += v3.w;
        }
        for (; j < n; j++) {
            int s0 = __shfl_sync(0xffffffff, idx, j);
            float4 v0 = *reinterpret_cast<const float4*>(x + (size_t)s0 * F_IN + lane * 4);
            a0.x += v0.x; a0.y += v0.y; a0.z += v0.z; a0.w += v0.w;
        }
    }
    a0.x += a1.x + a2.x + a3.x;
    a0.y += a1.y + a2.y + a3.y;
    a0.z += a1.z + a2.z + a3.z;
    a0.w += a1.w + a2.w + a3.w;

    // split to bf16 hi/lo, write 8B each
    __nv_bfloat16 h0b = __float2bfloat16(a0.x);
    __nv_bfloat16 h1b = __float2bfloat16(a0.y);
    __nv_bfloat16 h2b = __float2bfloat16(a0.z);
    __nv_bfloat16 h3b = __float2bfloat16(a0.w);
    uint2 hv, lv;
    hv.x = pack_bf2(h0b, h1b);
    hv.y = pack_bf2(h2b, h3b);
    lv.x = pack_bf2(__float2bfloat16(a0.x - __bfloat162float(h0b)),
                    __float2bfloat16(a0.y - __bfloat162float(h1b)));
    lv.y = pack_bf2(__float2bfloat16(a0.z - __bfloat162float(h2b)),
                    __float2bfloat16(a0.w - __bfloat162float(h3b)));
    *reinterpret_cast<uint2*>(h_hi + (size_t)warp * F_IN + lane * 4) = hv;
    *reinterpret_cast<uint2*>(h_lo + (size_t)warp * F_IN + lane * 4) = lv;
}

// ---------------------------------------------------------------------------
// Fused MLP: out = (relu(h0 @ W1 + b1)) @ W2 + b2, one CTA per 128-row block.
// A is pre-split bf16 hi/lo. h1 never leaves SMEM. 4 hidden-chunks of 128.
// ---------------------------------------------------------------------------
__global__ __launch_bounds__(256, 1)
void fused_mlp_kernel(const __nv_bfloat16* __restrict__ A_hi,
                      const __nv_bfloat16* __restrict__ A_lo,
                      const __nv_bfloat16* __restrict__ W1t_hi,
                      const __nv_bfloat16* __restrict__ W1t_lo,
                      const float* __restrict__ b1,
                      const __nv_bfloat16* __restrict__ W2t_hi,
                      const __nv_bfloat16* __restrict__ W2t_lo,
                      const float* __restrict__ b2,
                      float* __restrict__ out,
                      int M)
{
    constexpr int SM_A_HI = 0;
    constexpr int SM_A_LO = 32768;
    constexpr int SM_W_HI = 65536;
    constexpr int SM_W_LO = 65536 + 32768;
    constexpr int SM_H_HI = 131072;
    constexpr int SM_H_LO = 131072 + 32768;

    extern __shared__ __align__(1024) char smem[];
    const uint32_t sbase = smem_to_u32(smem);

    const int tid  = threadIdx.x;
    const int wid  = tid >> 5;
    const int lane = tid & 31;
    const int wm   = wid >> 2;
    const int wn   = wid & 3;
    const int bm   = blockIdx.x * 128;

    const int a_row = lane & 15;
    const int a_kh  = (lane >> 4) & 1;
    const int b_row = lane & 7;
    const int b_kh  = (lane >> 3) & 1;
    const int er    = lane >> 2;
    const int ec    = (lane & 3) * 2;

    // ---- stage A = pre-split h0 block [128 x 128] (uint4 copies) ----
    // 128 bf16 per row = 256 B = 16 uint4  -> 2048 slots, 8 iterations
    #pragma unroll
    for (int it = 0; it < 8; it++) {
        int slot = tid + it * 256;          // 2048 uint4 slots
        int r  = slot >> 4;                 // 16 uint4 per row
        int c8 = slot & 15;
        int gr = bm + r;
        uint4 hv, lv;
        if (gr < M) {
            hv = *reinterpret_cast<const uint4*>(A_hi + (size_t)gr * F_IN + c8 * 8);
            lv = *reinterpret_cast<const uint4*>(A_lo + (size_t)gr * F_IN + c8 * 8);
        } else {
            hv = make_uint4(0, 0, 0, 0); lv = make_uint4(0, 0, 0, 0);
        }
        uint32_t off = toff128(r, c8 * 8);
        *reinterpret_cast<uint4*>(smem + SM_A_HI + off) = hv;
        *reinterpret_cast<uint4*>(smem + SM_A_LO + off) = lv;
    }

    float acc_out[4][4][4];
    #pragma unroll
    for (int i = 0; i < 4; i++)
        #pragma unroll
        for (int j = 0; j < 4; j++)
            #pragma unroll
            for (int q = 0; q < 4; q++)
                acc_out[i][j][q] = 0.f;

    for (int c = 0; c < 4; c++) {
        __syncthreads();
        #pragma unroll
        for (int it = 0; it < 8; it++) {
            int slot = tid + it * 256;
            int r  = slot >> 4;
            int c8 = slot & 15;
            size_t g = (size_t)(c * 128 + r) * F_IN + c8 * 8;
            uint32_t off = toff128(r, c8 * 8);
            *reinterpret_cast<uint4*>(smem + SM_W_HI + off) =
                *reinterpret_cast<const uint4*>(W1t_hi + g);
            *reinterpret_cast<uint4*>(smem + SM_W_LO + off) =
                *reinterpret_cast<const uint4*>(W1t_lo + g);
        }
        __syncthreads();

        float acc_h[4][4][4];
        #pragma unroll
        for (int i = 0; i < 4; i++)
            #pragma unroll
            for (int j = 0; j < 4; j++)
                #pragma unroll
                for (int q = 0; q < 4; q++)
                    acc_h[i][j][q] = 0.f;

        #pragma unroll
        for (int ks = 0; ks < 8; ks++) {
            uint32_t bh[4][2], bl[4][2];
            #pragma unroll
            for (int nt = 0; nt < 4; nt++) {
                int n = wn * 32 + nt * 8 + b_row;
                uint32_t off = toff128(n, ks * 16 + b_kh * 8);
                ldmx2(bh[nt], sbase + SM_W_HI + off);
                ldmx2(bl[nt], sbase + SM_W_LO + off);
            }
            #pragma unroll
            for (int mt = 0; mt < 4; mt++) {
                int m = wm * 64 + mt * 16 + a_row;
                uint32_t off = toff128(m, ks * 16 + a_kh * 8);
                uint32_t ah[4], al[4];
                ldmx4(ah, sbase + SM_A_HI + off);
                ldmx4(al, sbase + SM_A_LO + off);
                #pragma unroll
                for (int nt = 0; nt < 4; nt++) {
                    mma16816(acc_h[mt][nt], ah, bh[nt]);
                    mma16816(acc_h[mt][nt], ah, bl[nt]);
                    mma16816(acc_h[mt][nt], al, bh[nt]);
                }
            }
        }
        __syncthreads();

        #pragma unroll
        for (int mt = 0; mt < 4; mt++) {
            int lr0 = wm * 64 + mt * 16 + er;
            #pragma unroll
            for (int nt = 0; nt < 4; nt++) {
                int lc = wn * 32 + nt * 8 + ec;
                float bia0 = b1[c * 128 + lc];
                float bia1 = b1[c * 128 + lc + 1];
                #pragma unroll
                for (int h = 0; h < 2; h++) {
                    float v0 = fmaxf(acc_h[mt][nt][2 * h + 0] + bia0, 0.f);
                    float v1 = fmaxf(acc_h[mt][nt][2 * h + 1] + bia1, 0.f);
                    __nv_bfloat16 hh0 = __float2bfloat16(v0);
                    __nv_bfloat16 hh1 = __float2bfloat16(v1);
                    uint32_t off = toff128(lr0 + h * 8, lc);
                    *reinterpret_cast<uint32_t*>(smem + SM_H_HI + off) = pack_bf2(hh0, hh1);
                    *reinterpret_cast<uint32_t*>(smem + SM_H_LO + off) =
                        pack_bf2(__float2bfloat16(v0 - __bfloat162float(hh0)),
                                 __float2bfloat16(v1 - __bfloat162float(hh1)));
                }
            }
        }
        #pragma unroll
        for (int it = 0; it < 8; it++) {
            int slot = tid + it * 256;
            int r  = slot >> 4;
            int c8 = slot & 15;
            size_t g = (size_t)r * F_HID + c * 128 + c8 * 8;
            uint32_t off = toff128(r, c8 * 8);
            *reinterpret_cast<uint4*>(smem + SM_W_HI + off) =
                *reinterpret_cast<const uint4*>(W2t_hi + g);
            *reinterpret_cast<uint4*>(smem + SM_W_LO + off) =
                *reinterpret_cast<const uint4*>(W2t_lo + g);
        }
        __syncthreads();

        #pragma unroll
        for (int ks = 0; ks < 8; ks++) {
            uint32_t bh[4][2], bl[4][2];
            #pragma unroll
            for (int nt = 0; nt < 4; nt++) {
                int n = wn * 32 + nt * 8 + b_row;
                uint32_t off = toff128(n, ks * 16 + b_kh * 8);
                ldmx2(bh[nt], sbase + SM_W_HI + off);
                ldmx2(bl[nt], sbase + SM_W_LO + off);
            }
            #pragma unroll
            for (int mt = 0; mt < 4; mt++) {
                int m = wm * 64 + mt * 16 + a_row;
                uint32_t off = toff128(m, ks * 16 + a_kh * 8);
                uint32_t ah[4], al[4];
                ldmx4(ah, sbase + SM_H_HI + off);
                ldmx4(al, sbase + SM_H_LO + off);
                #pragma unroll
                for (int nt = 0; nt < 4; nt++) {
                    mma16816(acc_out[mt][nt], ah, bh[nt]);
                    mma16816(acc_out[mt][nt], ah, bl[nt]);
                    mma16816(acc_out[mt][nt], al, bh[nt]);
                }
            }
        }
    }

    #pragma unroll
    for (int mt = 0; mt < 4; mt++) {
        const int row0 = bm + wm * 64 + mt * 16 + er;
        #pragma unroll
        for (int nt = 0; nt < 4; nt++) {
            const int col = wn * 32 + nt * 8 + ec;
            const float bia0 = b2[col], bia1 = b2[col + 1];
            #pragma unroll
            for (int h = 0; h < 2; h++) {
                const int row = row0 + h * 8;
                if (row >= M) continue;
                float2 v;
                v.x = acc_out[mt][nt][2 * h + 0] + bia0;
                v.y = acc_out[mt][nt][2 * h + 1] + bia1;
                *reinterpret_cast<float2*>(out + (size_t)row * F_IN + col) = v;
            }
        }
    }
}

// ---------------------------------------------------------------------------
// Launch
// ---------------------------------------------------------------------------
extern "C" void kernel_launch(void* const* d_in, const int* in_sizes, int n_in,
                              void* d_out, int out_size)
{
    const float* x   = (const float*)d_in[0];
    const void*  ei  = d_in[1];
    const float* W1  = (const float*)d_in[2];
    const float* b1  = (const float*)d_in[3];
    const float* W2  = (const float*)d_in[4];
    const float* b2  = (const float*)d_in[5];
    const float* eps = (const float*)d_in[6];
    float* out = (float*)d_out;

    const int n_edges = in_sizes[1] / 2;

    __nv_bfloat16 *h0hi, *h0lo, *w1th, *w1tl, *w2th, *w2tl;
    cudaGetSymbolAddress((void**)&h0hi, g_h0_hi);
    cudaGetSymbolAddress((void**)&h0lo, g_h0_lo);
    cudaGetSymbolAddress((void**)&w1th, g_w1t_hi);
    cudaGetSymbolAddress((void**)&w1tl, g_w1t_lo);
    cudaGetSymbolAddress((void**)&w2th, g_w2t_hi);
    cudaGetSymbolAddress((void**)&w2tl, g_w2t_lo);

    // 0) zero histogram + dtype detect; weight prep
    zero_deg_kernel<<<(N_NODES + 255) / 256, 256>>>((const int*)ei);
    transpose_split_kernel<<<(F_IN * F_HID + 255) / 256, 256>>>(W1, F_IN, F_HID, w1th, w1tl);
    transpose_split_kernel<<<(F_HID * F_IN + 255) / 256, 256>>>(W2, F_HID, F_IN, w2th, w2tl);

    // 1) counting sort of edges by dst
    hist_kernel<<<(n_edges + 1023) / 1024, 256>>>(ei, n_edges);
    scan_part_kernel<<<NPART, 256>>>();
    scan_mid_kernel<<<1, 256>>>();
    scan_final_kernel<<<NPART, 256>>>();
    bucket_kernel<<<(n_edges + 1023) / 1024, 256>>>(ei, n_edges);

    // 2) gather-accumulate -> split bf16 h0
    {
        const int wpb = 8;  // 256 threads, 8 warps/block
        gather_kernel<<<(N_NODES + wpb - 1) / wpb, wpb * 32>>>(x, eps, h0hi, h0lo);
    }

    // 3) fused MLP
    {
        constexpr int SMEM = 196608;   // 192 KB
        cudaFuncSetAttribute(fused_mlp_kernel,
                             cudaFuncAttributeMaxDynamicSharedMemorySize, SMEM);
        const int mtiles = (N_NODES + 127) / 128;   // 391
        fused_mlp_kernel<<<mtiles, 256, SMEM>>>(
            h0hi, h0lo, w1th, w1tl, b1, w2th, w2tl, b2, out, N_NODES);
    }
}

// round 10
// speedup vs baseline: 1.2843x; 1.0435x over previous
#include <cuda_runtime.h>
#include <cuda_bf16.h>
#include <cstdint>

#define N_NODES 50000
#define F_IN    128
#define F_HID   512
#define CAP     128            // fixed bucket capacity per node
#define MAX_OVF 4096           // overflow list capacity (never used in practice)

// ---------------------------------------------------------------------------
// Scratch (__device__ globals; allocation-free rule)
// ---------------------------------------------------------------------------
__device__ __align__(16) __nv_bfloat16 g_h0_hi[N_NODES * F_IN];       // split h0
__device__ __align__(16) __nv_bfloat16 g_h0_lo[N_NODES * F_IN];
__device__ __align__(16) __nv_bfloat16 g_w1t_hi[F_HID * F_IN];        // W1^T split [512,128]
__device__ __align__(16) __nv_bfloat16 g_w1t_lo[F_HID * F_IN];
__device__ __align__(16) __nv_bfloat16 g_w2t_hi[F_IN * F_HID];        // W2^T split [128,512]
__device__ __align__(16) __nv_bfloat16 g_w2t_lo[F_IN * F_HID];
__device__ int g_cur[N_NODES];                 // per-node fill counters (=degree)
__device__ int g_bucket[N_NODES * CAP];        // fixed-capacity buckets of src ids
__device__ int g_ovf[2 * MAX_OVF];             // overflow (src,dst) pairs
__device__ int g_ovf_cnt;
__device__ int g_idx_is64;

__device__ __forceinline__ uint32_t smem_to_u32(const void* p) {
    uint32_t a;
    asm("{ .reg .u64 t; cvta.to.shared.u64 t, %1; cvt.u32.u64 %0, t; }"
        : "=r"(a) : "l"(p));
    return a;
}
__device__ __forceinline__ uint32_t pack_bf2(__nv_bfloat16 a, __nv_bfloat16 b) {
    __nv_bfloat162 t(a, b);
    return *reinterpret_cast<uint32_t*>(&t);
}
__device__ __forceinline__ uint32_t sw128(uint32_t byte_off) {
    return byte_off ^ ((byte_off >> 3) & 0x70);
}
// 128x128 bf16 tile stored as two 128x64 column blocks (16KB each, 128B rows, SW128)
__device__ __forceinline__ uint32_t toff128(int r, int k) {
    return (uint32_t)((k >> 6) * 16384) + sw128((uint32_t)(r * 128 + (k & 63) * 2));
}

__device__ __forceinline__ void ldmx4(uint32_t* r, uint32_t addr) {
    asm volatile("ldmatrix.sync.aligned.m8n8.x4.shared.b16 {%0,%1,%2,%3}, [%4];"
                 : "=r"(r[0]), "=r"(r[1]), "=r"(r[2]), "=r"(r[3]) : "r"(addr));
}
__device__ __forceinline__ void ldmx2(uint32_t* r, uint32_t addr) {
    asm volatile("ldmatrix.sync.aligned.m8n8.x2.shared.b16 {%0,%1}, [%2];"
                 : "=r"(r[0]), "=r"(r[1]) : "r"(addr));
}
__device__ __forceinline__ void mma16816(float* c, const uint32_t* a, const uint32_t* b) {
    asm volatile(
        "mma.sync.aligned.m16n8k16.row.col.f32.bf16.bf16.f32 "
        "{%0,%1,%2,%3}, {%4,%5,%6,%7}, {%8,%9}, {%0,%1,%2,%3};"
        : "+f"(c[0]), "+f"(c[1]), "+f"(c[2]), "+f"(c[3])
        : "r"(a[0]), "r"(a[1]), "r"(a[2]), "r"(a[3]), "r"(b[0]), "r"(b[1]));
}

__device__ __forceinline__ int load_idx(const void* ei, int i) {
    return g_idx_is64 ? (int)((const long long*)ei)[i] : ((const int*)ei)[i];
}

// ---------------------------------------------------------------------------
// Kernel A: zero bucket counters + overflow counter + dtype detection
// ---------------------------------------------------------------------------
__global__ void zero_kernel(const int* __restrict__ ei_words)
{
    int i = blockIdx.x * blockDim.x + threadIdx.x;
    if (i < N_NODES) g_cur[i] = 0;
    if (i == 0) {
        g_ovf_cnt = 0;
        int is64 = 1;
        #pragma unroll
        for (int k = 0; k < 64; k++) {
            if (ei_words[2 * k + 1] != 0) { is64 = 0; break; }
        }
        g_idx_is64 = is64;
    }
}

// ---------------------------------------------------------------------------
// Kernel B: single-pass bucketing (atomicAdd doubles as histogram).
// Overflow (pos >= CAP) goes to a global list handled by fixup_kernel.
// ---------------------------------------------------------------------------
__global__ void bucket_kernel(const void* __restrict__ ei, int n_edges)
{
    int base = blockIdx.x * 1024;
    #pragma unroll
    for (int k = 0; k < 4; k++) {
        int e = base + k * 256 + threadIdx.x;
        if (e < n_edges) {
            int s = load_idx(ei, e);
            int d = load_idx(ei, n_edges + e);
            if (s >= 0 && s < N_NODES && d >= 0 && d < N_NODES) {
                int pos = atomicAdd(&g_cur[d], 1);
                if (pos < CAP) {
                    g_bucket[d * CAP + pos] = s;
                } else {
                    int o = atomicAdd(&g_ovf_cnt, 1);
                    if (o < MAX_OVF) {
                        g_ovf[2 * o] = s;
                        g_ovf[2 * o + 1] = d;
                    }
                }
            }
        }
    }
}

// ---------------------------------------------------------------------------
// Kernel: weight transpose + hi/lo bf16 split. out[n*K+k] = split(W[k*N+n]).
// ---------------------------------------------------------------------------
__global__ void transpose_split_kernel(const float* __restrict__ W, int K, int N,
                                       __nv_bfloat16* __restrict__ out_hi,
                                       __nv_bfloat16* __restrict__ out_lo)
{
    int idx = blockIdx.x * blockDim.x + threadIdx.x;
    if (idx >= K * N) return;
    int n = idx / K, k = idx % K;
    float v = W[(size_t)k * N + n];
    __nv_bfloat16 h = __float2bfloat16(v);
    out_hi[idx] = h;
    out_lo[idx] = __float2bfloat16(v - __bfloat162float(h));
}

// ---------------------------------------------------------------------------
// Kernel E: gather-accumulate, warp per node, lane-parallel index loads.
//   h0[n] = (1+eps)*x[n] + sum_{src in bucket(n)} x[src]  -> split bf16 hi/lo
// ---------------------------------------------------------------------------
__global__ __launch_bounds__(256)
void gather_kernel(const float* __restrict__ x,
                   const float* __restrict__ eps,
                   __nv_bfloat16* __restrict__ h_hi,
                   __nv_bfloat16* __restrict__ h_lo)
{
    const int warp = (blockIdx.x * blockDim.x + threadIdx.x) >> 5;
    if (warp >= N_NODES) return;
    const int lane = threadIdx.x & 31;

    const int deg  = min(g_cur[warp], CAP);
    const int base = warp * CAP;
    const float s = 1.0f + *eps;

    float4 xv = *reinterpret_cast<const float4*>(x + (size_t)warp * F_IN + lane * 4);
    float4 a0, a1, a2, a3;
    a0.x = xv.x * s; a0.y = xv.y * s; a0.z = xv.z * s; a0.w = xv.w * s;
    a1 = make_float4(0.f, 0.f, 0.f, 0.f);
    a2 = make_float4(0.f, 0.f, 0.f, 0.f);
    a3 = make_float4(0.f, 0.f, 0.f, 0.f);

    for (int b = 0; b < deg; b += 32) {
        const int n = min(32, deg - b);
        // lane-parallel, coalesced index load; broadcast via shfl
        int idx = (b + lane < deg) ? g_bucket[base + b + lane] : 0;
        int j = 0;
        for (; j + 3 < n; j += 4) {
            int s0 = __shfl_sync(0xffffffff, idx, j);
            int s1 = __shfl_sync(0xffffffff, idx, j + 1);
            int s2 = __shfl_sync(0xffffffff, idx, j + 2);
            int s3 = __shfl_sync(0xffffffff, idx, j + 3);
            float4 v0 = *reinterpret_cast<const float4*>(x + (size_t)s0 * F_IN + lane * 4);
            float4 v1 = *reinterpret_cast<const float4*>(x + (size_t)s1 * F_IN + lane * 4);
            float4 v2 = *reinterpret_cast<const float4*>(x + (size_t)s2 * F_IN + lane * 4);
            float4 v3 = *reinterpret_cast<const float4*>(x + (size_t)s3 * F_IN + lane * 4);
            a0.x += v0.x; a0.y += v0.y; a0.z += v0.z; a0.w += v0.w;
            a1.x += v1.x; a1.y += v1.y; a1.z += v1.z; a1.w += v1.w;
            a2.x += v2.x; a2.y += v2.y; a2.z += v2.z; a2.w += v2.w;
            a3.x += v3.x; a3.y += v3.y; a3.z += v3.z; a3.w += v3.w;
        }
        for (; j < n; j++) {
            int s0 = __shfl_sync(0xffffffff, idx, j);
            float4 v0 = *reinterpret_cast<const float4*>(x + (size_t)s0 * F_IN + lane * 4);
            a0.x += v0.x; a0.y += v0.y; a0.z += v0.z; a0.w += v0.w;
        }
    }
    a0.x += a1.x + a2.x + a3.x;
    a0.y += a1.y + a2.y + a3.y;
    a0.z += a1.z + a2.z + a3.z;
    a0.w += a1.w + a2.w + a3.w;

    // split to bf16 hi/lo, write 8B each
    __nv_bfloat16 h0b = __float2bfloat16(a0.x);
    __nv_bfloat16 h1b = __float2bfloat16(a0.y);
    __nv_bfloat16 h2b = __float2bfloat16(a0.z);
    __nv_bfloat16 h3b = __float2bfloat16(a0.w);
    uint2 hv, lv;
    hv.x = pack_bf2(h0b, h1b);
    hv.y = pack_bf2(h2b, h3b);
    lv.x = pack_bf2(__float2bfloat16(a0.x - __bfloat162float(h0b)),
                    __float2bfloat16(a0.y - __bfloat162float(h1b)));
    lv.y = pack_bf2(__float2bfloat16(a0.z - __bfloat162float(h2b)),
                    __float2bfloat16(a0.w - __bfloat162float(h3b)));
    *reinterpret_cast<uint2*>(h_hi + (size_t)warp * F_IN + lane * 4) = hv;
    *reinterpret_cast<uint2*>(h_lo + (size_t)warp * F_IN + lane * 4) = lv;
}

// ---------------------------------------------------------------------------
// Kernel F: overflow fixup (single warp, serial over overflow edges; count is
// 0 in practice). Adds x[src] into split h0[dst], race-free by serial order.
// ---------------------------------------------------------------------------
__global__ void fixup_kernel(const float* __restrict__ x,
                             __nv_bfloat16* __restrict__ h_hi,
                             __nv_bfloat16* __restrict__ h_lo)
{
    const int cnt = min(g_ovf_cnt, MAX_OVF);
    const int lane = threadIdx.x;
    for (int e = 0; e < cnt; e++) {
        int s = g_ovf[2 * e];
        int d = g_ovf[2 * e + 1];
        float4 xv = *reinterpret_cast<const float4*>(x + (size_t)s * F_IN + lane * 4);
        uint2 hv = *reinterpret_cast<uint2*>(h_hi + (size_t)d * F_IN + lane * 4);
        uint2 lv = *reinterpret_cast<uint2*>(h_lo + (size_t)d * F_IN + lane * 4);
        __nv_bfloat162 h01 = *reinterpret_cast<__nv_bfloat162*>(&hv.x);
        __nv_bfloat162 h23 = *reinterpret_cast<__nv_bfloat162*>(&hv.y);
        __nv_bfloat162 l01 = *reinterpret_cast<__nv_bfloat162*>(&lv.x);
        __nv_bfloat162 l23 = *reinterpret_cast<__nv_bfloat162*>(&lv.y);
        float f0 = __bfloat162float(h01.x) + __bfloat162float(l01.x) + xv.x;
        float f1 = __bfloat162float(h01.y) + __bfloat162float(l01.y) + xv.y;
        float f2 = __bfloat162float(h23.x) + __bfloat162float(l23.x) + xv.z;
        float f3 = __bfloat162float(h23.y) + __bfloat162float(l23.y) + xv.w;
        __nv_bfloat16 n0 = __float2bfloat16(f0);
        __nv_bfloat16 n1 = __float2bfloat16(f1);
        __nv_bfloat16 n2 = __float2bfloat16(f2);
        __nv_bfloat16 n3 = __float2bfloat16(f3);
        hv.x = pack_bf2(n0, n1);
        hv.y = pack_bf2(n2, n3);
        lv.x = pack_bf2(__float2bfloat16(f0 - __bfloat162float(n0)),
                        __float2bfloat16(f1 - __bfloat162float(n1)));
        lv.y = pack_bf2(__float2bfloat16(f2 - __bfloat162float(n2)),
                        __float2bfloat16(f3 - __bfloat162float(n3)));
        *reinterpret_cast<uint2*>(h_hi + (size_t)d * F_IN + lane * 4) = hv;
        *reinterpret_cast<uint2*>(h_lo + (size_t)d * F_IN + lane * 4) = lv;
        __syncwarp();
    }
}

// ---------------------------------------------------------------------------
// Fused MLP: out = (relu(h0 @ W1 + b1)) @ W2 + b2, one CTA per 128-row block.
// A is pre-split bf16 hi/lo. h1 never leaves SMEM. 4 hidden-chunks of 128.
// ---------------------------------------------------------------------------
__global__ __launch_bounds__(256, 1)
void fused_mlp_kernel(const __nv_bfloat16* __restrict__ A_hi,
                      const __nv_bfloat16* __restrict__ A_lo,
                      const __nv_bfloat16* __restrict__ W1t_hi,
                      const __nv_bfloat16* __restrict__ W1t_lo,
                      const float* __restrict__ b1,
                      const __nv_bfloat16* __restrict__ W2t_hi,
                      const __nv_bfloat16* __restrict__ W2t_lo,
                      const float* __restrict__ b2,
                      float* __restrict__ out,
                      int M)
{
    constexpr int SM_A_HI = 0;
    constexpr int SM_A_LO = 32768;
    constexpr int SM_W_HI = 65536;
    constexpr int SM_W_LO = 65536 + 32768;
    constexpr int SM_H_HI = 131072;
    constexpr int SM_H_LO = 131072 + 32768;

    extern __shared__ __align__(1024) char smem[];
    const uint32_t sbase = smem_to_u32(smem);

    const int tid  = threadIdx.x;
    const int wid  = tid >> 5;
    const int lane = tid & 31;
    const int wm   = wid >> 2;
    const int wn   = wid & 3;
    const int bm   = blockIdx.x * 128;

    const int a_row = lane & 15;
    const int a_kh  = (lane >> 4) & 1;
    const int b_row = lane & 7;
    const int b_kh  = (lane >> 3) & 1;
    const int er    = lane >> 2;
    const int ec    = (lane & 3) * 2;

    // ---- stage A = pre-split h0 block [128 x 128] (uint4 copies) ----
    #pragma unroll
    for (int it = 0; it < 8; it++) {
        int slot = tid + it * 256;          // 2048 uint4 slots
        int r  = slot >> 4;                 // 16 uint4 per row
        int c8 = slot & 15;
        int gr = bm + r;
        uint4 hv, lv;
        if (gr < M) {
            hv = *reinterpret_cast<const uint4*>(A_hi + (size_t)gr * F_IN + c8 * 8);
            lv = *reinterpret_cast<const uint4*>(A_lo + (size_t)gr * F_IN + c8 * 8);
        } else {
            hv = make_uint4(0, 0, 0, 0); lv = make_uint4(0, 0, 0, 0);
        }
        uint32_t off = toff128(r, c8 * 8);
        *reinterpret_cast<uint4*>(smem + SM_A_HI + off) = hv;
        *reinterpret_cast<uint4*>(smem + SM_A_LO + off) = lv;
    }

    float acc_out[4][4][4];
    #pragma unroll
    for (int i = 0; i < 4; i++)
        #pragma unroll
        for (int j = 0; j < 4; j++)
            #pragma unroll
            for (int q = 0; q < 4; q++)
                acc_out[i][j][q] = 0.f;

    for (int c = 0; c < 4; c++) {
        __syncthreads();
        #pragma unroll
        for (int it = 0; it < 8; it++) {
            int slot = tid + it * 256;
            int r  = slot >> 4;
            int c8 = slot & 15;
            size_t g = (size_t)(c * 128 + r) * F_IN + c8 * 8;
            uint32_t off = toff128(r, c8 * 8);
            *reinterpret_cast<uint4*>(smem + SM_W_HI + off) =
                *reinterpret_cast<const uint4*>(W1t_hi + g);
            *reinterpret_cast<uint4*>(smem + SM_W_LO + off) =
                *reinterpret_cast<const uint4*>(W1t_lo + g);
        }
        __syncthreads();

        float acc_h[4][4][4];
        #pragma unroll
        for (int i = 0; i < 4; i++)
            #pragma unroll
            for (int j = 0; j < 4; j++)
                #pragma unroll
                for (int q = 0; q < 4; q++)
                    acc_h[i][j][q] = 0.f;

        #pragma unroll
        for (int ks = 0; ks < 8; ks++) {
            uint32_t bh[4][2], bl[4][2];
            #pragma unroll
            for (int nt = 0; nt < 4; nt++) {
                int n = wn * 32 + nt * 8 + b_row;
                uint32_t off = toff128(n, ks * 16 + b_kh * 8);
                ldmx2(bh[nt], sbase + SM_W_HI + off);
                ldmx2(bl[nt], sbase + SM_W_LO + off);
            }
            #pragma unroll
            for (int mt = 0; mt < 4; mt++) {
                int m = wm * 64 + mt * 16 + a_row;
                uint32_t off = toff128(m, ks * 16 + a_kh * 8);
                uint32_t ah[4], al[4];
                ldmx4(ah, sbase + SM_A_HI + off);
                ldmx4(al, sbase + SM_A_LO + off);
                #pragma unroll
                for (int nt = 0; nt < 4; nt++) {
                    mma16816(acc_h[mt][nt], ah, bh[nt]);
                    mma16816(acc_h[mt][nt], ah, bl[nt]);
                    mma16816(acc_h[mt][nt], al, bh[nt]);
                }
            }
        }
        __syncthreads();

        #pragma unroll
        for (int mt = 0; mt < 4; mt++) {
            int lr0 = wm * 64 + mt * 16 + er;
            #pragma unroll
            for (int nt = 0; nt < 4; nt++) {
                int lc = wn * 32 + nt * 8 + ec;
                float bia0 = b1[c * 128 + lc];
                float bia1 = b1[c * 128 + lc + 1];
                #pragma unroll
                for (int h = 0; h < 2; h++) {
                    float v0 = fmaxf(acc_h[mt][nt][2 * h + 0] + bia0, 0.f);
                    float v1 = fmaxf(acc_h[mt][nt][2 * h + 1] + bia1, 0.f);
                    __nv_bfloat16 hh0 = __float2bfloat16(v0);
                    __nv_bfloat16 hh1 = __float2bfloat16(v1);
                    uint32_t off = toff128(lr0 + h * 8, lc);
                    *reinterpret_cast<uint32_t*>(smem + SM_H_HI + off) = pack_bf2(hh0, hh1);
                    *reinterpret_cast<uint32_t*>(smem + SM_H_LO + off) =
                        pack_bf2(__float2bfloat16(v0 - __bfloat162float(hh0)),
                                 __float2bfloat16(v1 - __bfloat162float(hh1)));
                }
            }
        }
        #pragma unroll
        for (int it = 0; it < 8; it++) {
            int slot = tid + it * 256;
            int r  = slot >> 4;
            int c8 = slot & 15;
            size_t g = (size_t)r * F_HID + c * 128 + c8 * 8;
            uint32_t off = toff128(r, c8 * 8);
            *reinterpret_cast<uint4*>(smem + SM_W_HI + off) =
                *reinterpret_cast<const uint4*>(W2t_hi + g);
            *reinterpret_cast<uint4*>(smem + SM_W_LO + off) =
                *reinterpret_cast<const uint4*>(W2t_lo + g);
        }
        __syncthreads();

        #pragma unroll
        for (int ks = 0; ks < 8; ks++) {
            uint32_t bh[4][2], bl[4][2];
            #pragma unroll
            for (int nt = 0; nt < 4; nt++) {
                int n = wn * 32 + nt * 8 + b_row;
                uint32_t off = toff128(n, ks * 16 + b_kh * 8);
                ldmx2(bh[nt], sbase + SM_W_HI + off);
                ldmx2(bl[nt], sbase + SM_W_LO + off);
            }
            #pragma unroll
            for (int mt = 0; mt < 4; mt++) {
                int m = wm * 64 + mt * 16 + a_row;
                uint32_t off = toff128(m, ks * 16 + a_kh * 8);
                uint32_t ah[4], al[4];
                ldmx4(ah, sbase + SM_H_HI + off);
                ldmx4(al, sbase + SM_H_LO + off);
                #pragma unroll
                for (int nt = 0; nt < 4; nt++) {
                    mma16816(acc_out[mt][nt], ah, bh[nt]);
                    mma16816(acc_out[mt][nt], ah, bl[nt]);
                    mma16816(acc_out[mt][nt], al, bh[nt]);
                }
            }
        }
    }

    #pragma unroll
    for (int mt = 0; mt < 4; mt++) {
        const int row0 = bm + wm * 64 + mt * 16 + er;
        #pragma unroll
        for (int nt = 0; nt < 4; nt++) {
            const int col = wn * 32 + nt * 8 + ec;
            const float bia0 = b2[col], bia1 = b2[col + 1];
            #pragma unroll
            for (int h = 0; h < 2; h++) {
                const int row = row0 + h * 8;
                if (row >= M) continue;
                float2 v;
                v.x = acc_out[mt][nt][2 * h + 0] + bia0;
                v.y = acc_out[mt][nt][2 * h + 1] + bia1;
                *reinterpret_cast<float2*>(out + (size_t)row * F_IN + col) = v;
            }
        }
    }
}

// ---------------------------------------------------------------------------
// Launch
// ---------------------------------------------------------------------------
extern "C" void kernel_launch(void* const* d_in, const int* in_sizes, int n_in,
                              void* d_out, int out_size)
{
    const float* x   = (const float*)d_in[0];
    const void*  ei  = d_in[1];
    const float* W1  = (const float*)d_in[2];
    const float* b1  = (const float*)d_in[3];
    const float* W2  = (const float*)d_in[4];
    const float* b2  = (const float*)d_in[5];
    const float* eps = (const float*)d_in[6];
    float* out = (float*)d_out;

    const int n_edges = in_sizes[1] / 2;

    __nv_bfloat16 *h0hi, *h0lo, *w1th, *w1tl, *w2th, *w2tl;
    cudaGetSymbolAddress((void**)&h0hi, g_h0_hi);
    cudaGetSymbolAddress((void**)&h0lo, g_h0_lo);
    cudaGetSymbolAddress((void**)&w1th, g_w1t_hi);
    cudaGetSymbolAddress((void**)&w1tl, g_w1t_lo);
    cudaGetSymbolAddress((void**)&w2th, g_w2t_hi);
    cudaGetSymbolAddress((void**)&w2tl, g_w2t_lo);

    // 0) zero counters + dtype detect; weight prep
    zero_kernel<<<(N_NODES + 255) / 256, 256>>>((const int*)ei);
    transpose_split_kernel<<<(F_IN * F_HID + 255) / 256, 256>>>(W1, F_IN, F_HID, w1th, w1tl);
    transpose_split_kernel<<<(F_HID * F_IN + 255) / 256, 256>>>(W2, F_HID, F_IN, w2th, w2tl);

    // 1) single-pass fixed-capacity bucketing
    bucket_kernel<<<(n_edges + 1023) / 1024, 256>>>(ei, n_edges);

    // 2) gather-accumulate -> split bf16 h0; then (empty) overflow fixup
    {
        const int wpb = 8;  // 256 threads, 8 warps/block
        gather_kernel<<<(N_NODES + wpb - 1) / wpb, wpb * 32>>>(x, eps, h0hi, h0lo);
        fixup_kernel<<<1, 32>>>(x, h0hi, h0lo);
    }

    // 3) fused MLP
    {
        constexpr int SMEM = 196608;   // 192 KB
        cudaFuncSetAttribute(fused_mlp_kernel,
                             cudaFuncAttributeMaxDynamicSharedMemorySize, SMEM);
        const int mtiles = (N_NODES + 127) / 128;   // 391
        fused_mlp_kernel<<<mtiles, 256, SMEM>>>(
            h0hi, h0lo, w1th, w1tl, b1, w2th, w2tl, b2, out, N_NODES);
    }
}

// round 11
// speedup vs baseline: 1.3278x; 1.0339x over previous
#include <cuda_runtime.h>
#include <cuda_bf16.h>
#include <cstdint>

#define N_NODES 50000
#define F_IN    128
#define F_HID   512
#define CAP     128            // fixed bucket capacity per node
#define MAX_OVF 4096           // overflow list capacity (never used in practice)

// ---------------------------------------------------------------------------
// Scratch (__device__ globals; allocation-free rule)
// ---------------------------------------------------------------------------
__device__ __align__(16) __nv_bfloat16 g_h0_hi[N_NODES * F_IN];       // split h0
__device__ __align__(16) __nv_bfloat16 g_h0_lo[N_NODES * F_IN];
__device__ __align__(16) __nv_bfloat16 g_w1t_hi[F_HID * F_IN];        // W1^T split [512,128]
__device__ __align__(16) __nv_bfloat16 g_w1t_lo[F_HID * F_IN];
__device__ __align__(16) __nv_bfloat16 g_w2t_hi[F_IN * F_HID];        // W2^T split [128,512]
__device__ __align__(16) __nv_bfloat16 g_w2t_lo[F_IN * F_HID];
__device__ int g_cur[N_NODES];                 // per-node fill counters (=degree)
__device__ int g_bucket[N_NODES * CAP];        // fixed-capacity buckets of src ids
__device__ int g_ovf[2 * MAX_OVF];             // overflow (src,dst) pairs
__device__ int g_ovf_cnt;
__device__ int g_idx_is64;

__device__ __forceinline__ uint32_t smem_to_u32(const void* p) {
    uint32_t a;
    asm("{ .reg .u64 t; cvta.to.shared.u64 t, %1; cvt.u32.u64 %0, t; }"
        : "=r"(a) : "l"(p));
    return a;
}
__device__ __forceinline__ uint32_t pack_bf2(__nv_bfloat16 a, __nv_bfloat16 b) {
    __nv_bfloat162 t(a, b);
    return *reinterpret_cast<uint32_t*>(&t);
}
__device__ __forceinline__ uint32_t sw128(uint32_t byte_off) {
    return byte_off ^ ((byte_off >> 3) & 0x70);
}
// 128x128 bf16 tile: two 128x64 column blocks (16KB each, 128B rows, SW128)
__device__ __forceinline__ uint32_t toff128(int r, int k) {
    return (uint32_t)((k >> 6) * 16384) + sw128((uint32_t)(r * 128 + (k & 63) * 2));
}
// 64x128 bf16 tile (W1 chunk): two 64x64 column blocks (8KB each)
__device__ __forceinline__ uint32_t t64r(int r, int k) {
    return (uint32_t)((k >> 6) * 8192) + sw128((uint32_t)(r * 128 + (k & 63) * 2));
}
// 128x64 bf16 tile (H, W2 chunk): single block, 128B rows
__device__ __forceinline__ uint32_t t64c(int r, int k) {
    return sw128((uint32_t)(r * 128 + k * 2));
}

__device__ __forceinline__ void ldmx4(uint32_t* r, uint32_t addr) {
    asm volatile("ldmatrix.sync.aligned.m8n8.x4.shared.b16 {%0,%1,%2,%3}, [%4];"
                 : "=r"(r[0]), "=r"(r[1]), "=r"(r[2]), "=r"(r[3]) : "r"(addr));
}
__device__ __forceinline__ void ldmx2(uint32_t* r, uint32_t addr) {
    asm volatile("ldmatrix.sync.aligned.m8n8.x2.shared.b16 {%0,%1}, [%2];"
                 : "=r"(r[0]), "=r"(r[1]) : "r"(addr));
}
__device__ __forceinline__ void mma16816(float* c, const uint32_t* a, const uint32_t* b) {
    asm volatile(
        "mma.sync.aligned.m16n8k16.row.col.f32.bf16.bf16.f32 "
        "{%0,%1,%2,%3}, {%4,%5,%6,%7}, {%8,%9}, {%0,%1,%2,%3};"
        : "+f"(c[0]), "+f"(c[1]), "+f"(c[2]), "+f"(c[3])
        : "r"(a[0]), "r"(a[1]), "r"(a[2]), "r"(a[3]), "r"(b[0]), "r"(b[1]));
}
#define CP_ASYNC16(dst_u32, src_ptr) \
    asm volatile("cp.async.cg.shared.global [%0], [%1], 16;" \
                 :: "r"(dst_u32), "l"(src_ptr) : "memory")
#define CP_COMMIT() asm volatile("cp.async.commit_group;" ::: "memory")
#define CP_WAIT1()  asm volatile("cp.async.wait_group 1;"  ::: "memory")

__device__ __forceinline__ int load_idx(const void* ei, int i) {
    return g_idx_is64 ? (int)((const long long*)ei)[i] : ((const int*)ei)[i];
}

// ---------------------------------------------------------------------------
// Kernel A: zero bucket counters + overflow counter + dtype detection
// ---------------------------------------------------------------------------
__global__ void zero_kernel(const int* __restrict__ ei_words)
{
    int i = blockIdx.x * blockDim.x + threadIdx.x;
    if (i < N_NODES) g_cur[i] = 0;
    if (i == 0) {
        g_ovf_cnt = 0;
        int is64 = 1;
        #pragma unroll
        for (int k = 0; k < 64; k++) {
            if (ei_words[2 * k + 1] != 0) { is64 = 0; break; }
        }
        g_idx_is64 = is64;
    }
}

// ---------------------------------------------------------------------------
// Kernel B: single-pass bucketing (atomicAdd doubles as histogram).
// ---------------------------------------------------------------------------
__global__ void bucket_kernel(const void* __restrict__ ei, int n_edges)
{
    int base = blockIdx.x * 1024;
    #pragma unroll
    for (int k = 0; k < 4; k++) {
        int e = base + k * 256 + threadIdx.x;
        if (e < n_edges) {
            int s = load_idx(ei, e);
            int d = load_idx(ei, n_edges + e);
            if (s >= 0 && s < N_NODES && d >= 0 && d < N_NODES) {
                int pos = atomicAdd(&g_cur[d], 1);
                if (pos < CAP) {
                    g_bucket[d * CAP + pos] = s;
                } else {
                    int o = atomicAdd(&g_ovf_cnt, 1);
                    if (o < MAX_OVF) {
                        g_ovf[2 * o] = s;
                        g_ovf[2 * o + 1] = d;
                    }
                }
            }
        }
    }
}

// ---------------------------------------------------------------------------
// Kernel: weight transpose + hi/lo bf16 split. out[n*K+k] = split(W[k*N+n]).
// ---------------------------------------------------------------------------
__global__ void transpose_split_kernel(const float* __restrict__ W, int K, int N,
                                       __nv_bfloat16* __restrict__ out_hi,
                                       __nv_bfloat16* __restrict__ out_lo)
{
    int idx = blockIdx.x * blockDim.x + threadIdx.x;
    if (idx >= K * N) return;
    int n = idx / K, k = idx % K;
    float v = W[(size_t)k * N + n];
    __nv_bfloat16 h = __float2bfloat16(v);
    out_hi[idx] = h;
    out_lo[idx] = __float2bfloat16(v - __bfloat162float(h));
}

// ---------------------------------------------------------------------------
// Kernel E: gather-accumulate, warp per node, lane-parallel index loads.
// ---------------------------------------------------------------------------
__global__ __launch_bounds__(256)
void gather_kernel(const float* __restrict__ x,
                   const float* __restrict__ eps,
                   __nv_bfloat16* __restrict__ h_hi,
                   __nv_bfloat16* __restrict__ h_lo)
{
    const int warp = (blockIdx.x * blockDim.x + threadIdx.x) >> 5;
    if (warp >= N_NODES) return;
    const int lane = threadIdx.x & 31;

    const int deg  = min(g_cur[warp], CAP);
    const int base = warp * CAP;
    const float s = 1.0f + *eps;

    float4 xv = *reinterpret_cast<const float4*>(x + (size_t)warp * F_IN + lane * 4);
    float4 a0, a1, a2, a3;
    a0.x = xv.x * s; a0.y = xv.y * s; a0.z = xv.z * s; a0.w = xv.w * s;
    a1 = make_float4(0.f, 0.f, 0.f, 0.f);
    a2 = make_float4(0.f, 0.f, 0.f, 0.f);
    a3 = make_float4(0.f, 0.f, 0.f, 0.f);

    for (int b = 0; b < deg; b += 32) {
        const int n = min(32, deg - b);
        int idx = (b + lane < deg) ? g_bucket[base + b + lane] : 0;
        int j = 0;
        for (; j + 3 < n; j += 4) {
            int s0 = __shfl_sync(0xffffffff, idx, j);
            int s1 = __shfl_sync(0xffffffff, idx, j + 1);
            int s2 = __shfl_sync(0xffffffff, idx, j + 2);
            int s3 = __shfl_sync(0xffffffff, idx, j + 3);
            float4 v0 = *reinterpret_cast<const float4*>(x + (size_t)s0 * F_IN + lane * 4);
            float4 v1 = *reinterpret_cast<const float4*>(x + (size_t)s1 * F_IN + lane * 4);
            float4 v2 = *reinterpret_cast<const float4*>(x + (size_t)s2 * F_IN + lane * 4);
            float4 v3 = *reinterpret_cast<const float4*>(x + (size_t)s3 * F_IN + lane * 4);
            a0.x += v0.x; a0.y += v0.y; a0.z += v0.z; a0.w += v0.w;
            a1.x += v1.x; a1.y += v1.y; a1.z += v1.z; a1.w += v1.w;
            a2.x += v2.x; a2.y += v2.y; a2.z += v2.z; a2.w += v2.w;
            a3.x += v3.x; a3.y += v3.y; a3.z += v3.z; a3.w += v3.w;
        }
        for (; j < n; j++) {
            int s0 = __shfl_sync(0xffffffff, idx, j);
            float4 v0 = *reinterpret_cast<const float4*>(x + (size_t)s0 * F_IN + lane * 4);
            a0.x += v0.x; a0.y += v0.y; a0.z += v0.z; a0.w += v0.w;
        }
    }
    a0.x += a1.x + a2.x + a3.x;
    a0.y += a1.y + a2.y + a3.y;
    a0.z += a1.z + a2.z + a3.z;
    a0.w += a1.w + a2.w + a3.w;

    __nv_bfloat16 h0b = __float2bfloat16(a0.x);
    __nv_bfloat16 h1b = __float2bfloat16(a0.y);
    __nv_bfloat16 h2b = __float2bfloat16(a0.z);
    __nv_bfloat16 h3b = __float2bfloat16(a0.w);
    uint2 hv, lv;
    hv.x = pack_bf2(h0b, h1b);
    hv.y = pack_bf2(h2b, h3b);
    lv.x = pack_bf2(__float2bfloat16(a0.x - __bfloat162float(h0b)),
                    __float2bfloat16(a0.y - __bfloat162float(h1b)));
    lv.y = pack_bf2(__float2bfloat16(a0.z - __bfloat162float(h2b)),
                    __float2bfloat16(a0.w - __bfloat162float(h3b)));
    *reinterpret_cast<uint2*>(h_hi + (size_t)warp * F_IN + lane * 4) = hv;
    *reinterpret_cast<uint2*>(h_lo + (size_t)warp * F_IN + lane * 4) = lv;
}

// ---------------------------------------------------------------------------
// Kernel F: overflow fixup (single warp, serial; empty in practice).
// ---------------------------------------------------------------------------
__global__ void fixup_kernel(const float* __restrict__ x,
                             __nv_bfloat16* __restrict__ h_hi,
                             __nv_bfloat16* __restrict__ h_lo)
{
    const int cnt = min(g_ovf_cnt, MAX_OVF);
    const int lane = threadIdx.x;
    for (int e = 0; e < cnt; e++) {
        int s = g_ovf[2 * e];
        int d = g_ovf[2 * e + 1];
        float4 xv = *reinterpret_cast<const float4*>(x + (size_t)s * F_IN + lane * 4);
        uint2 hv = *reinterpret_cast<uint2*>(h_hi + (size_t)d * F_IN + lane * 4);
        uint2 lv = *reinterpret_cast<uint2*>(h_lo + (size_t)d * F_IN + lane * 4);
        __nv_bfloat162 h01 = *reinterpret_cast<__nv_bfloat162*>(&hv.x);
        __nv_bfloat162 h23 = *reinterpret_cast<__nv_bfloat162*>(&hv.y);
        __nv_bfloat162 l01 = *reinterpret_cast<__nv_bfloat162*>(&lv.x);
        __nv_bfloat162 l23 = *reinterpret_cast<__nv_bfloat162*>(&lv.y);
        float f0 = __bfloat162float(h01.x) + __bfloat162float(l01.x) + xv.x;
        float f1 = __bfloat162float(h01.y) + __bfloat162float(l01.y) + xv.y;
        float f2 = __bfloat162float(h23.x) + __bfloat162float(l23.x) + xv.z;
        float f3 = __bfloat162float(h23.y) + __bfloat162float(l23.y) + xv.w;
        __nv_bfloat16 n0 = __float2bfloat16(f0);
        __nv_bfloat16 n1 = __float2bfloat16(f1);
        __nv_bfloat16 n2 = __float2bfloat16(f2);
        __nv_bfloat16 n3 = __float2bfloat16(f3);
        hv.x = pack_bf2(n0, n1);
        hv.y = pack_bf2(n2, n3);
        lv.x = pack_bf2(__float2bfloat16(f0 - __bfloat162float(n0)),
                        __float2bfloat16(f1 - __bfloat162float(n1)));
        lv.y = pack_bf2(__float2bfloat16(f2 - __bfloat162float(n2)),
                        __float2bfloat16(f3 - __bfloat162float(n3)));
        *reinterpret_cast<uint2*>(h_hi + (size_t)d * F_IN + lane * 4) = hv;
        *reinterpret_cast<uint2*>(h_lo + (size_t)d * F_IN + lane * 4) = lv;
        __syncwarp();
    }
}

// ---------------------------------------------------------------------------
// Fused MLP with cp.async double-buffered weights.
// 8 hidden-chunks of 64. Per chunk: GEMM1 (128x64, K=128) -> H; GEMM2
// (128x128, K=64) accumulates out. W2[c] streams during GEMM1; W1[c+1]
// streams during GEMM2. SMEM 160KB, occ 1, 256 threads.
// ---------------------------------------------------------------------------
__global__ __launch_bounds__(256, 1)
void fused_mlp_kernel(const __nv_bfloat16* __restrict__ A_hi,
                      const __nv_bfloat16* __restrict__ A_lo,
                      const __nv_bfloat16* __restrict__ W1t_hi,
                      const __nv_bfloat16* __restrict__ W1t_lo,
                      const float* __restrict__ b1,
                      const __nv_bfloat16* __restrict__ W2t_hi,
                      const __nv_bfloat16* __restrict__ W2t_lo,
                      const float* __restrict__ b2,
                      float* __restrict__ out,
                      int M)
{
    constexpr int SM_A_HI  = 0;          // 32KB (128x128)
    constexpr int SM_A_LO  = 32768;      // 32KB
    constexpr int SM_H_HI  = 65536;      // 16KB (128x64)
    constexpr int SM_H_LO  = 81920;      // 16KB
    constexpr int SM_W1_HI = 98304;      // 16KB (64x128)
    constexpr int SM_W1_LO = 98304 + 16384;
    constexpr int SM_W2_HI = 131072;     // 16KB (128x64)
    constexpr int SM_W2_LO = 131072 + 16384;

    extern __shared__ __align__(1024) char smem[];
    const uint32_t sbase = smem_to_u32(smem);

    const int tid  = threadIdx.x;
    const int wid  = tid >> 5;
    const int lane = tid & 31;
    const int bm   = blockIdx.x * 128;

    // GEMM1 warp layout: 4m x 2n (warp tile 32x32)
    const int wm1 = wid >> 1;
    const int wn1 = wid & 1;
    // GEMM2 warp layout: 2m x 4n (warp tile 64x32)
    const int wm2 = wid >> 2;
    const int wn2 = wid & 3;

    const int a_row = lane & 15;
    const int a_kh  = (lane >> 4) & 1;
    const int b_row = lane & 7;
    const int b_kh  = (lane >> 3) & 1;
    const int er    = lane >> 2;
    const int ec    = (lane & 3) * 2;

    // ---- preload W1 chunk 0 via cp.async ----
    {
        #pragma unroll
        for (int it = 0; it < 4; it++) {
            int slot = tid + it * 256;      // 1024 slots: 64 rows x 16 uint4
            int r  = slot >> 4;
            int c8 = slot & 15;
            uint32_t off = t64r(r, c8 * 8);
            CP_ASYNC16(sbase + SM_W1_HI + off, W1t_hi + (size_t)r * F_IN + c8 * 8);
            CP_ASYNC16(sbase + SM_W1_LO + off, W1t_lo + (size_t)r * F_IN + c8 * 8);
        }
        CP_COMMIT();
    }

    // ---- stage A = pre-split h0 block [128 x 128] ----
    #pragma unroll
    for (int it = 0; it < 8; it++) {
        int slot = tid + it * 256;          // 2048 uint4 slots
        int r  = slot >> 4;
        int c8 = slot & 15;
        int gr = bm + r;
        uint4 hv, lv;
        if (gr < M) {
            hv = *reinterpret_cast<const uint4*>(A_hi + (size_t)gr * F_IN + c8 * 8);
            lv = *reinterpret_cast<const uint4*>(A_lo + (size_t)gr * F_IN + c8 * 8);
        } else {
            hv = make_uint4(0, 0, 0, 0); lv = make_uint4(0, 0, 0, 0);
        }
        uint32_t off = toff128(r, c8 * 8);
        *reinterpret_cast<uint4*>(smem + SM_A_HI + off) = hv;
        *reinterpret_cast<uint4*>(smem + SM_A_LO + off) = lv;
    }

    float acc_out[4][4][4];
    #pragma unroll
    for (int i = 0; i < 4; i++)
        #pragma unroll
        for (int j = 0; j < 4; j++)
            #pragma unroll
            for (int q = 0; q < 4; q++)
                acc_out[i][j][q] = 0.f;

    for (int c = 0; c < 8; c++) {           // 8 hidden chunks of 64
        __syncthreads();                    // GEMM2(c-1) readers done (W2 buf, H)

        // stream W2[c]: 128 rows x 64 k
        #pragma unroll
        for (int it = 0; it < 4; it++) {
            int slot = tid + it * 256;      // 1024 slots: 128 rows x 8 uint4
            int r  = slot >> 3;
            int c8 = slot & 7;
            uint32_t off = t64c(r, c8 * 8);
            const size_t g = (size_t)r * F_HID + c * 64 + c8 * 8;
            CP_ASYNC16(sbase + SM_W2_HI + off, W2t_hi + g);
            CP_ASYNC16(sbase + SM_W2_LO + off, W2t_lo + g);
        }
        CP_COMMIT();
        CP_WAIT1();                         // W1[c] arrived (own ops)
        __syncthreads();                    // publish W1[c]

        // ---- GEMM1: H = A @ W1c  (out 128x64, K=128) ----
        float acc_h[2][4][4];
        #pragma unroll
        for (int i = 0; i < 2; i++)
            #pragma unroll
            for (int j = 0; j < 4; j++)
                #pragma unroll
                for (int q = 0; q < 4; q++)
                    acc_h[i][j][q] = 0.f;

        #pragma unroll
        for (int ks = 0; ks < 8; ks++) {
            uint32_t bh[4][2], bl[4][2];
            #pragma unroll
            for (int nt = 0; nt < 4; nt++) {
                int n = wn1 * 32 + nt * 8 + b_row;
                uint32_t off = t64r(n, ks * 16 + b_kh * 8);
                ldmx2(bh[nt], sbase + SM_W1_HI + off);
                ldmx2(bl[nt], sbase + SM_W1_LO + off);
            }
            #pragma unroll
            for (int mt = 0; mt < 2; mt++) {
                int m = wm1 * 32 + mt * 16 + a_row;
                uint32_t off = toff128(m, ks * 16 + a_kh * 8);
                uint32_t ah[4], al[4];
                ldmx4(ah, sbase + SM_A_HI + off);
                ldmx4(al, sbase + SM_A_LO + off);
                #pragma unroll
                for (int nt = 0; nt < 4; nt++) {
                    mma16816(acc_h[mt][nt], ah, bh[nt]);
                    mma16816(acc_h[mt][nt], ah, bl[nt]);
                    mma16816(acc_h[mt][nt], al, bh[nt]);
                }
            }
        }
        __syncthreads();                    // all warps done reading W1 buf

        // prefetch W1[c+1] into the freed W1 buffer
        if (c + 1 < 8) {
            #pragma unroll
            for (int it = 0; it < 4; it++) {
                int slot = tid + it * 256;
                int r  = slot >> 4;
                int c8 = slot & 15;
                uint32_t off = t64r(r, c8 * 8);
                const size_t g = (size_t)((c + 1) * 64 + r) * F_IN + c8 * 8;
                CP_ASYNC16(sbase + SM_W1_HI + off, W1t_hi + g);
                CP_ASYNC16(sbase + SM_W1_LO + off, W1t_lo + g);
            }
        }
        CP_COMMIT();                        // (empty group when c==7)

        // bias + relu + split -> H
        #pragma unroll
        for (int mt = 0; mt < 2; mt++) {
            int lr0 = wm1 * 32 + mt * 16 + er;
            #pragma unroll
            for (int nt = 0; nt < 4; nt++) {
                int lc = wn1 * 32 + nt * 8 + ec;
                float bia0 = b1[c * 64 + lc];
                float bia1 = b1[c * 64 + lc + 1];
                #pragma unroll
                for (int h = 0; h < 2; h++) {
                    float v0 = fmaxf(acc_h[mt][nt][2 * h + 0] + bia0, 0.f);
                    float v1 = fmaxf(acc_h[mt][nt][2 * h + 1] + bia1, 0.f);
                    __nv_bfloat16 hh0 = __float2bfloat16(v0);
                    __nv_bfloat16 hh1 = __float2bfloat16(v1);
                    uint32_t off = t64c(lr0 + h * 8, lc);
                    *reinterpret_cast<uint32_t*>(smem + SM_H_HI + off) = pack_bf2(hh0, hh1);
                    *reinterpret_cast<uint32_t*>(smem + SM_H_LO + off) =
                        pack_bf2(__float2bfloat16(v0 - __bfloat162float(hh0)),
                                 __float2bfloat16(v1 - __bfloat162float(hh1)));
                }
            }
        }
        CP_WAIT1();                         // W2[c] arrived (own ops)
        __syncthreads();                    // publish H + W2[c]

        // ---- GEMM2: out += H @ W2c  (out 128x128, K=64) ----
        #pragma unroll
        for (int ks = 0; ks < 4; ks++) {
            uint32_t bh[4][2], bl[4][2];
            #pragma unroll
            for (int nt = 0; nt < 4; nt++) {
                int n = wn2 * 32 + nt * 8 + b_row;
                uint32_t off = t64c(n, ks * 16 + b_kh * 8);
                ldmx2(bh[nt], sbase + SM_W2_HI + off);
                ldmx2(bl[nt], sbase + SM_W2_LO + off);
            }
            #pragma unroll
            for (int mt = 0; mt < 4; mt++) {
                int m = wm2 * 64 + mt * 16 + a_row;
                uint32_t off = t64c(m, ks * 16 + a_kh * 8);
                uint32_t ah[4], al[4];
                ldmx4(ah, sbase + SM_H_HI + off);
                ldmx4(al, sbase + SM_H_LO + off);
                #pragma unroll
                for (int nt = 0; nt < 4; nt++) {
                    mma16816(acc_out[mt][nt], ah, bh[nt]);
                    mma16816(acc_out[mt][nt], ah, bl[nt]);
                    mma16816(acc_out[mt][nt], al, bh[nt]);
                }
            }
        }
    }

    // ---- epilogue: out + b2, fp32 ----
    #pragma unroll
    for (int mt = 0; mt < 4; mt++) {
        const int row0 = bm + wm2 * 64 + mt * 16 + er;
        #pragma unroll
        for (int nt = 0; nt < 4; nt++) {
            const int col = wn2 * 32 + nt * 8 + ec;
            const float bia0 = b2[col], bia1 = b2[col + 1];
            #pragma unroll
            for (int h = 0; h < 2; h++) {
                const int row = row0 + h * 8;
                if (row >= M) continue;
                float2 v;
                v.x = acc_out[mt][nt][2 * h + 0] + bia0;
                v.y = acc_out[mt][nt][2 * h + 1] + bia1;
                *reinterpret_cast<float2*>(out + (size_t)row * F_IN + col) = v;
            }
        }
    }
}

// ---------------------------------------------------------------------------
// Launch
// ---------------------------------------------------------------------------
extern "C" void kernel_launch(void* const* d_in, const int* in_sizes, int n_in,
                              void* d_out, int out_size)
{
    const float* x   = (const float*)d_in[0];
    const void*  ei  = d_in[1];
    const float* W1  = (const float*)d_in[2];
    const float* b1  = (const float*)d_in[3];
    const float* W2  = (const float*)d_in[4];
    const float* b2  = (const float*)d_in[5];
    const float* eps = (const float*)d_in[6];
    float* out = (float*)d_out;

    const int n_edges = in_sizes[1] / 2;

    __nv_bfloat16 *h0hi, *h0lo, *w1th, *w1tl, *w2th, *w2tl;
    cudaGetSymbolAddress((void**)&h0hi, g_h0_hi);
    cudaGetSymbolAddress((void**)&h0lo, g_h0_lo);
    cudaGetSymbolAddress((void**)&w1th, g_w1t_hi);
    cudaGetSymbolAddress((void**)&w1tl, g_w1t_lo);
    cudaGetSymbolAddress((void**)&w2th, g_w2t_hi);
    cudaGetSymbolAddress((void**)&w2tl, g_w2t_lo);

    // 0) zero counters + dtype detect; weight prep
    zero_kernel<<<(N_NODES + 255) / 256, 256>>>((const int*)ei);
    transpose_split_kernel<<<(F_IN * F_HID + 255) / 256, 256>>>(W1, F_IN, F_HID, w1th, w1tl);
    transpose_split_kernel<<<(F_HID * F_IN + 255) / 256, 256>>>(W2, F_HID, F_IN, w2th, w2tl);

    // 1) single-pass fixed-capacity bucketing
    bucket_kernel<<<(n_edges + 1023) / 1024, 256>>>(ei, n_edges);

    // 2) gather-accumulate -> split bf16 h0; then (empty) overflow fixup
    {
        const int wpb = 8;
        gather_kernel<<<(N_NODES + wpb - 1) / wpb, wpb * 32>>>(x, eps, h0hi, h0lo);
        fixup_kernel<<<1, 32>>>(x, h0hi, h0lo);
    }

    // 3) fused MLP (cp.async double-buffered weights)
    {
        constexpr int SMEM = 163840;   // 160 KB
        cudaFuncSetAttribute(fused_mlp_kernel,
                             cudaFuncAttributeMaxDynamicSharedMemorySize, SMEM);
        const int mtiles = (N_NODES + 127) / 128;   // 391
        fused_mlp_kernel<<<mtiles, 256, SMEM>>>(
            h0hi, h0lo, w1th, w1tl, b1, w2th, w2tl, b2, out, N_NODES);
    }
}